// round 9
// baseline (speedup 1.0000x reference)
#include <cuda_runtime.h>
#include <cuda_bf16.h>
#include <cstdint>

// ---------------------------------------------------------------------------
// RelationNetwork v9.
// k0 : fp32 -> bf16 hi/lo split of [roi; q_w; k_w; out_w]
// k13: UBER-KERNEL. blocks [0,192): K1 mma GEMM; blocks [192,1216): K3a
//      pos-proj stream -> logw fp32. Tensor + DRAM overlap in one launch.
// K2 : mma.sync 3-term: aff = 0.125 * Q K^T (occupancy 2)
// K3b: softmax(logw + aff) -> soft bf16 hi/lo (load-hoisted, high MLP)
// K4 : out = soft @ P^T via mma.sync 3-term (64n tiles, 256 blocks)
// ---------------------------------------------------------------------------

__device__ float g_aff [1024u * 16u * 1024u];            // 64 MB [n][g][m]
__device__ float g_logw[1024u * 16u * 1024u];            // 64 MB [n][g][m]
__device__ __nv_bfloat16 g_hi [4096u * 1024u];           // input hi split
__device__ __nv_bfloat16 g_lo [4096u * 1024u];           // input lo split
__device__ __nv_bfloat16 g_qkh[2u * 16u * 1024u * 64u];  // Q,K hi [seg][g][n][64]
__device__ __nv_bfloat16 g_qkl[2u * 16u * 1024u * 64u];  // Q,K lo
__device__ __nv_bfloat16 g_ph [16u * 64u * 1024u];       // P^T hi [g][o][k]
__device__ __nv_bfloat16 g_pl [16u * 64u * 1024u];       // P^T lo
__device__ __nv_bfloat16 g_sh [16u * 1024u * 1024u];     // soft hi [g][n][m]
__device__ __nv_bfloat16 g_sl [16u * 1024u * 1024u];     // soft lo

// ---- packed f32x2 helpers ---------------------------------------------------
__device__ __forceinline__ unsigned long long pack2(float a, float b) {
    unsigned long long r;
    asm("mov.b64 %0, {%1, %2};" : "=l"(r)
        : "r"(__float_as_uint(a)), "r"(__float_as_uint(b)));
    return r;
}
__device__ __forceinline__ void unpack2(unsigned long long v, float& a, float& b) {
    unsigned int lo, hi;
    asm("mov.b64 {%0, %1}, %2;" : "=r"(lo), "=r"(hi) : "l"(v));
    a = __uint_as_float(lo);
    b = __uint_as_float(hi);
}
__device__ __forceinline__ unsigned long long fma2(unsigned long long a,
                                                   unsigned long long b,
                                                   unsigned long long c) {
    unsigned long long d;
    asm("fma.rn.f32x2 %0, %1, %2, %3;" : "=l"(d) : "l"(a), "l"(b), "l"(c));
    return d;
}

// ---- mma.sync / cp.async helpers --------------------------------------------
__device__ __forceinline__ uint32_t smem_u32(const void* p) {
    uint32_t a;
    asm("{ .reg .u64 t; cvta.to.shared.u64 t, %1; cvt.u32.u64 %0, t; }"
        : "=r"(a) : "l"(p));
    return a;
}
#define CP16(s, g) \
    asm volatile("cp.async.cg.shared.global [%0], [%1], 16;" \
                 :: "r"(s), "l"(g) : "memory")
#define CP_COMMIT() asm volatile("cp.async.commit_group;" ::: "memory")
#define CP_WAIT(n)  asm volatile("cp.async.wait_group %0;" :: "n"(n) : "memory")
#define LDSM4(r, a) \
    asm volatile("ldmatrix.sync.aligned.m8n8.x4.shared.b16 {%0,%1,%2,%3}, [%4];" \
                 : "=r"((r)[0]), "=r"((r)[1]), "=r"((r)[2]), "=r"((r)[3]) \
                 : "r"(a))
#define MMA_BF16(d, a, b0, b1) \
    asm volatile("mma.sync.aligned.m16n8k16.row.col.f32.bf16.bf16.f32 " \
                 "{%0,%1,%2,%3}, {%4,%5,%6,%7}, {%8,%9}, {%0,%1,%2,%3};" \
                 : "+f"((d)[0]), "+f"((d)[1]), "+f"((d)[2]), "+f"((d)[3]) \
                 : "r"((a)[0]), "r"((a)[1]), "r"((a)[2]), "r"((a)[3]), \
                   "r"(b0), "r"(b1))

// 64B-row swizzle: 4 chunks of 16B permuted by row pair.
__device__ __forceinline__ uint32_t swz(int r, int c) {
    return (uint32_t)(r * 64 + (((c ^ ((r >> 1) & 3)) & 3) << 4));
}
// 128B-row SW128 swizzle (K2 tiles).
__device__ __forceinline__ uint32_t sw128(uint32_t off) {
    return off ^ ((off >> 3) & 0x70);
}

// ---------------------------------------------------------------------------
// k0: split [roi; q_w; k_w; out_w] into bf16 hi + lo.
// ---------------------------------------------------------------------------
__global__ __launch_bounds__(256) void k0_convert(
    const float* __restrict__ roi, const float* __restrict__ qw,
    const float* __restrict__ kw,  const float* __restrict__ ow)
{
    const size_t e = ((size_t)blockIdx.x * 256 + threadIdx.x) * 4;
    const float* src;
    size_t off;
    if (e < (1u << 20))      { src = roi; off = e; }
    else if (e < (2u << 20)) { src = qw;  off = e - (1u << 20); }
    else if (e < (3u << 20)) { src = kw;  off = e - (2u << 20); }
    else                     { src = ow;  off = e - (3u << 20); }
    const float4 v = *(const float4*)(src + off);
    float x[4] = {v.x, v.y, v.z, v.w};
    __nv_bfloat16 h[4], l[4];
#pragma unroll
    for (int i = 0; i < 4; i++) {
        h[i] = __float2bfloat16(x[i]);
        l[i] = __float2bfloat16(x[i] - __bfloat162float(h[i]));
    }
    ((__nv_bfloat162*)(g_hi + e))[0] = __nv_bfloat162(h[0], h[1]);
    ((__nv_bfloat162*)(g_hi + e))[1] = __nv_bfloat162(h[2], h[3]);
    ((__nv_bfloat162*)(g_lo + e))[0] = __nv_bfloat162(l[0], l[1]);
    ((__nv_bfloat162*)(g_lo + e))[1] = __nv_bfloat162(l[2], l[3]);
}

// ---------------------------------------------------------------------------
// K1 path pieces (used inside k13).
// ---------------------------------------------------------------------------
#define K1_STAGE 32768
#define K1_DSMEM 67584        // max(2 stages = 64K, transpose 128x132 f32)

__device__ __forceinline__ void k1_issue(uint32_t so, int row0, int col0,
                                         int kc, int tid)
{
#pragma unroll
    for (int j = 0; j < 2; j++) {
        const int id = tid + (j << 8);
        const int r = id >> 2, c = id & 3;
        const uint32_t s = so + swz(r, c);
        const size_t goA = (size_t)(row0 + r) * 1024 + (kc << 5) + (c << 3);
        const size_t goB = (size_t)(1024 + col0 + r) * 1024 + (kc << 5) + (c << 3);
        CP16(s,         g_hi + goA);
        CP16(s +  8192, g_lo + goA);
        CP16(s + 16384, g_hi + goB);
        CP16(s + 24576, g_lo + goB);
    }
    CP_COMMIT();
}

__device__ __forceinline__ void k1_compute(uint32_t so, float acc[4][4][4],
                                           int wm, int wn, int lane)
{
    const int arow = lane & 15;
    const int achk = lane >> 4;
#pragma unroll
    for (int ks = 0; ks < 2; ks++) {
        uint32_t ah[4][4], al[4][4], bh[2][4], bl[2][4];
#pragma unroll
        for (int mi = 0; mi < 4; mi++) {
            const int r = wm * 64 + mi * 16 + arow;
            const uint32_t addr = so + swz(r, ks * 2 + achk);
            LDSM4(ah[mi], addr);
            LDSM4(al[mi], addr + 8192);
        }
#pragma unroll
        for (int nj = 0; nj < 2; nj++) {
            const int r = wn * 32 + nj * 16 + arow;
            const uint32_t addr = so + 16384 + swz(r, ks * 2 + achk);
            LDSM4(bh[nj], addr);
            LDSM4(bl[nj], addr + 8192);
        }
#pragma unroll
        for (int mi = 0; mi < 4; mi++)
#pragma unroll
            for (int n = 0; n < 4; n++) {
                const int nj = n >> 1, sb = n & 1;
                MMA_BF16(acc[mi][n], ah[mi], bh[nj][sb], bh[nj][sb + 2]);
                MMA_BF16(acc[mi][n], ah[mi], bl[nj][sb], bl[nj][sb + 2]);
                MMA_BF16(acc[mi][n], al[mi], bh[nj][sb], bh[nj][sb + 2]);
            }
    }
}

// ---------------------------------------------------------------------------
// k13: uber-kernel. blocks [0,192) = K1 GEMM; blocks [192,1216) = K3a stream.
// ---------------------------------------------------------------------------
__global__ __launch_bounds__(256, 2) void k13(
    const float* __restrict__ qb, const float* __restrict__ kb,
    const float* __restrict__ pe, const float* __restrict__ pw,
    const float* __restrict__ pb)
{
    extern __shared__ char sm1[];
    const int tid = threadIdx.x;

    if (blockIdx.x < 192) {
        // =========================== K1 path ================================
        __shared__ float sbias[128];
        const uint32_t sbase = smem_u32(sm1);
        const int lane = tid & 31, wid = tid >> 5;
        const int wm = wid >> 2, wn = wid & 3;
        const int col0 = (blockIdx.x % 24) << 7;
        const int row0 = (blockIdx.x / 24) << 7;
        const int seg = col0 >> 10, jb0 = col0 & 1023;

        if (tid < 128)
            sbias[tid] = (seg == 0) ? qb[jb0 + tid]
                       : ((seg == 1) ? kb[jb0 + tid] : 0.0f);

        float acc[4][4][4];
#pragma unroll
        for (int i = 0; i < 4; i++)
#pragma unroll
            for (int j = 0; j < 4; j++)
#pragma unroll
                for (int q = 0; q < 4; q++) acc[i][j][q] = 0.0f;

        k1_issue(sbase, row0, col0, 0, tid);

#pragma unroll 1
        for (int kc = 0; kc < 32; kc++) {
            const uint32_t so = sbase + ((kc & 1) ? (uint32_t)K1_STAGE : 0u);
            if (kc < 31) {
                k1_issue(sbase + (((kc + 1) & 1) ? (uint32_t)K1_STAGE : 0u),
                         row0, col0, kc + 1, tid);
                CP_WAIT(1);
            } else {
                CP_WAIT(0);
            }
            __syncthreads();
            k1_compute(so, acc, wm, wn, lane);
            __syncthreads();
        }

        if (seg < 2) {
#pragma unroll
            for (int mi = 0; mi < 4; mi++) {
                const int r0 = row0 + wm * 64 + mi * 16 + (lane >> 2);
#pragma unroll
                for (int n = 0; n < 4; n++) {
                    const int lc = wn * 32 + n * 8 + ((lane & 3) << 1);
                    const int jl = jb0 + lc;
                    const int g = jl >> 6, d0 = jl & 63;
                    const float b0 = sbias[lc], b1 = sbias[lc + 1];
                    const float f00 = acc[mi][n][0] + b0;
                    const float f01 = acc[mi][n][1] + b1;
                    const float f10 = acc[mi][n][2] + b0;
                    const float f11 = acc[mi][n][3] + b1;
                    const size_t bi = ((size_t)(seg * 16 + g) * 1024) * 64 + d0;
                    __nv_bfloat16 h00 = __float2bfloat16(f00);
                    __nv_bfloat16 h01 = __float2bfloat16(f01);
                    __nv_bfloat16 h10 = __float2bfloat16(f10);
                    __nv_bfloat16 h11 = __float2bfloat16(f11);
                    *(__nv_bfloat162*)(g_qkh + bi + (size_t)r0 * 64) =
                        __nv_bfloat162(h00, h01);
                    *(__nv_bfloat162*)(g_qkh + bi + (size_t)(r0 + 8) * 64) =
                        __nv_bfloat162(h10, h11);
                    *(__nv_bfloat162*)(g_qkl + bi + (size_t)r0 * 64) =
                        __nv_bfloat162(
                            __float2bfloat16(f00 - __bfloat162float(h00)),
                            __float2bfloat16(f01 - __bfloat162float(h01)));
                    *(__nv_bfloat162*)(g_qkl + bi + (size_t)(r0 + 8) * 64) =
                        __nv_bfloat162(
                            __float2bfloat16(f10 - __bfloat162float(h10)),
                            __float2bfloat16(f11 - __bfloat162float(h11)));
                }
            }
        } else {
            // transpose through smem: smf[col][row] stride 132
            float* smf = (float*)sm1;
#pragma unroll
            for (int mi = 0; mi < 4; mi++) {
                const int rl = wm * 64 + mi * 16 + (lane >> 2);
#pragma unroll
                for (int n = 0; n < 4; n++) {
                    const int lc = wn * 32 + n * 8 + ((lane & 3) << 1);
                    smf[lc * 132 + rl]           = acc[mi][n][0];
                    smf[(lc + 1) * 132 + rl]     = acc[mi][n][1];
                    smf[lc * 132 + rl + 8]       = acc[mi][n][2];
                    smf[(lc + 1) * 132 + rl + 8] = acc[mi][n][3];
                }
            }
            __syncthreads();
            const int c = tid >> 1, half = tid & 1;
            const int jl = jb0 + c;
            const int g = jl >> 6, o = jl & 63;
            __nv_bfloat16* dh = g_ph + ((size_t)g * 64 + o) * 1024 +
                                row0 + half * 64;
            __nv_bfloat16* dl = g_pl + ((size_t)g * 64 + o) * 1024 +
                                row0 + half * 64;
            const float* srow = smf + c * 132 + half * 64;
#pragma unroll
            for (int i4 = 0; i4 < 16; i4++) {
                const float4 v = *(const float4*)(srow + i4 * 4);
                __nv_bfloat16 h0 = __float2bfloat16(v.x);
                __nv_bfloat16 h1 = __float2bfloat16(v.y);
                __nv_bfloat16 h2 = __float2bfloat16(v.z);
                __nv_bfloat16 h3 = __float2bfloat16(v.w);
                ((__nv_bfloat162*)(dh + i4 * 4))[0] = __nv_bfloat162(h0, h1);
                ((__nv_bfloat162*)(dh + i4 * 4))[1] = __nv_bfloat162(h2, h3);
                ((__nv_bfloat162*)(dl + i4 * 4))[0] = __nv_bfloat162(
                    __float2bfloat16(v.x - __bfloat162float(h0)),
                    __float2bfloat16(v.y - __bfloat162float(h1)));
                ((__nv_bfloat162*)(dl + i4 * 4))[1] = __nv_bfloat162(
                    __float2bfloat16(v.z - __bfloat162float(h2)),
                    __float2bfloat16(v.w - __bfloat162float(h3)));
            }
        }
    } else {
        // =========================== K3a path ===============================
        // logw[n][g][m] = log(max(pos_w@pe + pos_b, 1e-6))
        __shared__ ulonglong2 swd2[16][32];
        __shared__ float sb3[16];
        const int n = blockIdx.x - 192;

        for (int idx = tid; idx < 1024; idx += 256) {
            const float w = pw[idx];
            ((unsigned long long*)swd2)[idx] = pack2(w, w);
        }
        if (tid < 16) sb3[tid] = pb[tid];
        __syncthreads();

        const int m0 = tid << 2;
        unsigned long long acc[16][2];
#pragma unroll
        for (int gg = 0; gg < 16; gg++) { acc[gg][0] = 0ULL; acc[gg][1] = 0ULL; }

        const float* base = pe + (size_t)n * 1024 + m0;
        ulonglong2 cur[8];
#pragma unroll
        for (int j = 0; j < 8; j++)
            cur[j] = __ldg((const ulonglong2*)(base + (size_t)j * 1048576));

#pragma unroll 1
        for (int e0 = 0; e0 < 64; e0 += 8) {
            ulonglong2 nxt[8];
            const int eb = (e0 + 8) & 63;   // wrap: final reload hits L2
#pragma unroll
            for (int j = 0; j < 8; j++)
                nxt[j] = __ldg((const ulonglong2*)
                               (base + (size_t)(eb + j) * 1048576));
#pragma unroll
            for (int j = 0; j < 8; j += 2) {
                const ulonglong2 c0 = cur[j], c1 = cur[j + 1];
                const int ep = (e0 + j) >> 1;
#pragma unroll
                for (int gg = 0; gg < 16; gg++) {
                    const ulonglong2 w = swd2[gg][ep];
                    acc[gg][0] = fma2(w.x, c0.x, acc[gg][0]);
                    acc[gg][0] = fma2(w.y, c1.x, acc[gg][0]);
                    acc[gg][1] = fma2(w.x, c0.y, acc[gg][1]);
                    acc[gg][1] = fma2(w.y, c1.y, acc[gg][1]);
                }
            }
#pragma unroll
            for (int j = 0; j < 8; j++) cur[j] = nxt[j];
        }

        float* lwp = g_logw + (size_t)n * 16 * 1024 + m0;
#pragma unroll
        for (int gg = 0; gg < 16; gg++) {
            float x0, x1, x2, x3;
            unpack2(acc[gg][0], x0, x1);
            unpack2(acc[gg][1], x2, x3);
            const float bgg = sb3[gg];
            float4 o;
            o.x = __logf(fmaxf(x0 + bgg, 1e-6f));
            o.y = __logf(fmaxf(x1 + bgg, 1e-6f));
            o.z = __logf(fmaxf(x2 + bgg, 1e-6f));
            o.w = __logf(fmaxf(x3 + bgg, 1e-6f));
            *(float4*)(lwp + (size_t)gg * 1024) = o;
        }
    }
}

// ---------------------------------------------------------------------------
// K2: aff = 0.125 * Q K^T via mma.sync split. One g per block, 128x128, K=64.
// Occupancy 2 so the single-shot 64KB cp.async prologue overlaps across CTAs.
// ---------------------------------------------------------------------------
#define K2_DSMEM 65536

__global__ __launch_bounds__(256, 2) void k2_mma()
{
    extern __shared__ char sm2[];
    const uint32_t sbase = smem_u32(sm2);
    const int tid = threadIdx.x, lane = tid & 31, wid = tid >> 5;
    const int wm = wid >> 2, wn = wid & 3;
    const int m0 = blockIdx.x << 7, n0 = blockIdx.y << 7, g = blockIdx.z;

    const __nv_bfloat16* srcs[4] = {
        g_qkh + ((size_t)g * 1024 + n0) * 64,
        g_qkl + ((size_t)g * 1024 + n0) * 64,
        g_qkh + ((size_t)(16 + g) * 1024 + m0) * 64,
        g_qkl + ((size_t)(16 + g) * 1024 + m0) * 64
    };
#pragma unroll
    for (int i = 0; i < 16; i++) {
        const int idx = tid + (i << 8);
        const int buf = idx >> 10, j = idx & 1023;
        const int r = j >> 3, c = j & 7;
        CP16(sbase + buf * 16384 + sw128((r << 7) + (c << 4)),
             srcs[buf] + (size_t)r * 64 + (c << 3));
    }
    CP_COMMIT();
    CP_WAIT(0);
    __syncthreads();

    float acc[4][4][4];
#pragma unroll
    for (int i = 0; i < 4; i++)
#pragma unroll
        for (int j = 0; j < 4; j++)
#pragma unroll
            for (int q = 0; q < 4; q++) acc[i][j][q] = 0.0f;

    const int arow = lane & 15, achk = lane >> 4;
#pragma unroll
    for (int ks = 0; ks < 4; ks++) {
        uint32_t ah[4][4], al[4][4], bh[2][4], bl[2][4];
#pragma unroll
        for (int mi = 0; mi < 4; mi++) {
            const int r = wm * 64 + mi * 16 + arow;
            const uint32_t addr =
                sbase + sw128((r << 7) + (ks << 5) + (achk << 4));
            LDSM4(ah[mi], addr);
            LDSM4(al[mi], addr + 16384);
        }
#pragma unroll
        for (int nj = 0; nj < 2; nj++) {
            const int r = wn * 32 + nj * 16 + arow;
            const uint32_t addr =
                sbase + 32768 + sw128((r << 7) + (ks << 5) + (achk << 4));
            LDSM4(bh[nj], addr);
            LDSM4(bl[nj], addr + 16384);
        }
#pragma unroll
        for (int mi = 0; mi < 4; mi++)
#pragma unroll
            for (int n = 0; n < 4; n++) {
                const int nj = n >> 1, sb = n & 1;
                MMA_BF16(acc[mi][n], ah[mi], bh[nj][sb], bh[nj][sb + 2]);
                MMA_BF16(acc[mi][n], ah[mi], bl[nj][sb], bl[nj][sb + 2]);
                MMA_BF16(acc[mi][n], al[mi], bh[nj][sb], bh[nj][sb + 2]);
            }
    }

#pragma unroll
    for (int mi = 0; mi < 4; mi++) {
        const int r0 = n0 + wm * 64 + mi * 16 + (lane >> 2);
#pragma unroll
        for (int n = 0; n < 4; n++) {
            const int mc = m0 + wn * 32 + n * 8 + ((lane & 3) << 1);
            *(float2*)(g_aff + ((size_t)r0 * 16 + g) * 1024 + mc) =
                make_float2(acc[mi][n][0] * 0.125f, acc[mi][n][1] * 0.125f);
            *(float2*)(g_aff + ((size_t)(r0 + 8) * 16 + g) * 1024 + mc) =
                make_float2(acc[mi][n][2] * 0.125f, acc[mi][n][3] * 0.125f);
        }
    }
}

// ---------------------------------------------------------------------------
// K3b: soft = softmax(logw + aff) -> bf16 hi/lo. Load-hoisted 3-pass:
// per-pass, ALL per-thread loads+local reductions run before ANY shfl chain
// (shfl.sync fences the scheduler; keeping it out of the load loop gives
// MLP ~16 instead of ~2).
// ---------------------------------------------------------------------------
__global__ __launch_bounds__(256, 3) void k3b_softmax()
{
    __shared__ float red[16][8];
    const int n = blockIdx.x;
    const int t = threadIdx.x;
    const int m0 = t << 2;
    const int lane = t & 31, wid = t >> 5;

    const float* lwp = g_logw + (size_t)n * 16 * 1024 + m0;
    const float* afp = g_aff  + (size_t)n * 16 * 1024 + m0;

    // pass 1: per-thread max (pure loads), then reductions
    float mx[16];
#pragma unroll
    for (int gg = 0; gg < 16; gg++) {
        const float4 a = *(const float4*)(lwp + (size_t)gg * 1024);
        const float4 b = *(const float4*)(afp + (size_t)gg * 1024);
        mx[gg] = fmaxf(fmaxf(a.x + b.x, a.y + b.y),
                       fmaxf(a.z + b.z, a.w + b.w));
    }
#pragma unroll
    for (int gg = 0; gg < 16; gg++) {
        float m = mx[gg];
#pragma unroll
        for (int off = 16; off > 0; off >>= 1)
            m = fmaxf(m, __shfl_xor_sync(0xffffffffu, m, off));
        mx[gg] = m;
    }
    if (lane == 0) {
#pragma unroll
        for (int gg = 0; gg < 16; gg++) red[gg][wid] = mx[gg];
    }
    __syncthreads();
#pragma unroll
    for (int gg = 0; gg < 16; gg++) {
        float m = red[gg][0];
#pragma unroll
        for (int w = 1; w < 8; w++) m = fmaxf(m, red[gg][w]);
        mx[gg] = m;
    }
    __syncthreads();

    // pass 2: per-thread sum (loads hot in L1/L2), then reductions
    float inv[16];
#pragma unroll
    for (int gg = 0; gg < 16; gg++) {
        const float4 a = *(const float4*)(lwp + (size_t)gg * 1024);
        const float4 b = *(const float4*)(afp + (size_t)gg * 1024);
        inv[gg] = __expf(a.x + b.x - mx[gg]) + __expf(a.y + b.y - mx[gg]) +
                  __expf(a.z + b.z - mx[gg]) + __expf(a.w + b.w - mx[gg]);
    }
#pragma unroll
    for (int gg = 0; gg < 16; gg++) {
        float s = inv[gg];
#pragma unroll
        for (int off = 16; off > 0; off >>= 1)
            s += __shfl_xor_sync(0xffffffffu, s, off);
        inv[gg] = s;
    }
    if (lane == 0) {
#pragma unroll
        for (int gg = 0; gg < 16; gg++) red[gg][wid] = inv[gg];
    }
    __syncthreads();
#pragma unroll
    for (int gg = 0; gg < 16; gg++) {
        float s = red[gg][0];
#pragma unroll
        for (int w = 1; w < 8; w++) s += red[gg][w];
        inv[gg] = __fdividef(1.0f, s);
    }

    // pass 3: scale + bf16 hi/lo store
#pragma unroll
    for (int gg = 0; gg < 16; gg++) {
        const float4 a = *(const float4*)(lwp + (size_t)gg * 1024);
        const float4 b = *(const float4*)(afp + (size_t)gg * 1024);
        const float v0 = __expf(a.x + b.x - mx[gg]) * inv[gg];
        const float v1 = __expf(a.y + b.y - mx[gg]) * inv[gg];
        const float v2 = __expf(a.z + b.z - mx[gg]) * inv[gg];
        const float v3 = __expf(a.w + b.w - mx[gg]) * inv[gg];
        const __nv_bfloat16 h0 = __float2bfloat16(v0);
        const __nv_bfloat16 h1 = __float2bfloat16(v1);
        const __nv_bfloat16 h2 = __float2bfloat16(v2);
        const __nv_bfloat16 h3 = __float2bfloat16(v3);
        const size_t so = ((size_t)gg * 1024 + n) * 1024 + m0;
        ((__nv_bfloat162*)(g_sh + so))[0] = __nv_bfloat162(h0, h1);
        ((__nv_bfloat162*)(g_sh + so))[1] = __nv_bfloat162(h2, h3);
        ((__nv_bfloat162*)(g_sl + so))[0] = __nv_bfloat162(
            __float2bfloat16(v0 - __bfloat162float(h0)),
            __float2bfloat16(v1 - __bfloat162float(h1)));
        ((__nv_bfloat162*)(g_sl + so))[1] = __nv_bfloat162(
            __float2bfloat16(v2 - __bfloat162float(h2)),
            __float2bfloat16(v3 - __bfloat162float(h3)));
    }
}

// ---------------------------------------------------------------------------
// K4: out[n][g*64+o] = sum_k soft[g][n][k] * P^T[g][o][k] + out_b.
// 64n x 64o block (256 blocks -> full chip), BK=32, 2-stage cp.async.
// 8 warps (2m x 4n) -> warp tile 32n x 16o.
// Stage: Ah 4K | Al 4K | Bh 4K | Bl 4K = 16K; 2 stages = 32K.
// ---------------------------------------------------------------------------
#define K4_STAGE 16384
#define K4_DSMEM (2 * K4_STAGE)

__device__ __forceinline__ void k4_issue(uint32_t so, int n0, int g,
                                         int kt, int tid)
{
    const int r = tid >> 2, c = tid & 3;
    const uint32_t s = so + swz(r, c);
    const size_t ga = ((size_t)g * 1024 + n0 + r) * 1024 + kt + (c << 3);
    CP16(s,        g_sh + ga);
    CP16(s + 4096, g_sl + ga);
    const size_t gb = ((size_t)g * 64 + r) * 1024 + kt + (c << 3);
    CP16(s + 8192,  g_ph + gb);
    CP16(s + 12288, g_pl + gb);
    CP_COMMIT();
}

__global__ __launch_bounds__(256, 2) void k4_mma(float* __restrict__ out,
                                                 const float* __restrict__ obias)
{
    extern __shared__ char sm4[];
    __shared__ float sbias[64];
    const uint32_t sbase = smem_u32(sm4);
    const int tid = threadIdx.x, lane = tid & 31, wid = tid >> 5;
    const int wm = wid >> 2, wn = wid & 3;
    const int n0 = blockIdx.x << 6, g = blockIdx.y;

    if (tid < 64) sbias[tid] = obias[(g << 6) + tid];

    float acc[2][2][4];
#pragma unroll
    for (int i = 0; i < 2; i++)
#pragma unroll
        for (int j = 0; j < 2; j++)
#pragma unroll
            for (int q = 0; q < 4; q++) acc[i][j][q] = 0.0f;

    k4_issue(sbase, n0, g, 0, tid);

    const int arow = lane & 15, achk = lane >> 4;
#pragma unroll 1
    for (int kc = 0; kc < 32; kc++) {
        const uint32_t so = sbase + ((kc & 1) ? (uint32_t)K4_STAGE : 0u);
        if (kc < 31) {
            k4_issue(sbase + (((kc + 1) & 1) ? (uint32_t)K4_STAGE : 0u),
                     n0, g, (kc + 1) << 5, tid);
            CP_WAIT(1);
        } else {
            CP_WAIT(0);
        }
        __syncthreads();
#pragma unroll
        for (int ks = 0; ks < 2; ks++) {
            uint32_t ah[2][4], al[2][4], bh[4], bl[4];
#pragma unroll
            for (int mi = 0; mi < 2; mi++) {
                const int r = wm * 32 + mi * 16 + arow;
                const uint32_t addr = so + swz(r, ks * 2 + achk);
                LDSM4(ah[mi], addr);
                LDSM4(al[mi], addr + 4096);
            }
            {
                const int r = wn * 16 + arow;
                const uint32_t addr = so + 8192 + swz(r, ks * 2 + achk);
                LDSM4(bh, addr);
                LDSM4(bl, addr + 4096);
            }
#pragma unroll
            for (int mi = 0; mi < 2; mi++)
#pragma unroll
                for (int n = 0; n < 2; n++) {
                    MMA_BF16(acc[mi][n], ah[mi], bh[n], bh[n + 2]);
                    MMA_BF16(acc[mi][n], ah[mi], bl[n], bl[n + 2]);
                    MMA_BF16(acc[mi][n], al[mi], bh[n], bh[n + 2]);
                }
        }
        __syncthreads();
    }

#pragma unroll
    for (int mi = 0; mi < 2; mi++) {
        const int r0 = n0 + wm * 32 + mi * 16 + (lane >> 2);
#pragma unroll
        for (int n = 0; n < 2; n++) {
            const int lc = wn * 16 + n * 8 + ((lane & 3) << 1);
            const float b0 = sbias[lc], b1 = sbias[lc + 1];
            float* dst = out + (size_t)r0 * 1024 + (g << 6) + lc;
            dst[0] = acc[mi][n][0] + b0;
            dst[1] = acc[mi][n][1] + b1;
            dst[1024 * 8 + 0] = acc[mi][n][2] + b0;
            dst[1024 * 8 + 1] = acc[mi][n][3] + b1;
        }
    }
}

// ---------------------------------------------------------------------------
extern "C" void kernel_launch(void* const* d_in, const int* in_sizes, int n_in,
                              void* d_out, int out_size)
{
    const float* roi = (const float*)d_in[0];
    const float* pe  = (const float*)d_in[1];
    int ix = 2;
    if (ix < n_in && in_sizes[ix] == 1) ix++;
    const float* pos_w = (const float*)d_in[ix++];
    const float* pos_b = (const float*)d_in[ix++];
    const float* q_w   = (const float*)d_in[ix++];
    const float* q_b   = (const float*)d_in[ix++];
    const float* k_w   = (const float*)d_in[ix++];
    const float* k_b   = (const float*)d_in[ix++];
    const float* out_w = (const float*)d_in[ix++];
    const float* out_b = (const float*)d_in[ix++];
    float* out = (float*)d_out;

    cudaFuncSetAttribute(k13, cudaFuncAttributeMaxDynamicSharedMemorySize,
                         K1_DSMEM);
    cudaFuncSetAttribute(k2_mma, cudaFuncAttributeMaxDynamicSharedMemorySize,
                         K2_DSMEM);
    cudaFuncSetAttribute(k4_mma, cudaFuncAttributeMaxDynamicSharedMemorySize,
                         K4_DSMEM);

    k0_convert <<<4096,           256>>>(roi, q_w, k_w, out_w);
    k13        <<<1216,           256, K1_DSMEM>>>(q_b, k_b, pe, pos_w, pos_b);
    k2_mma     <<<dim3(8, 8, 16), 256, K2_DSMEM>>>();
    k3b_softmax<<<1024,           256>>>();
    k4_mma     <<<dim3(16, 16),   256, K4_DSMEM>>>(out, out_b);
}

// round 10
// speedup vs baseline: 1.1087x; 1.1087x over previous
#include <cuda_runtime.h>
#include <cuda_bf16.h>
#include <cstdint>

// ---------------------------------------------------------------------------
// RelationNetwork v10.
// k0 : fp32 -> bf16 hi/lo split of [roi; q_w; k_w; out_w]
// k13: UBER-KERNEL. blocks [0,192): K1 mma GEMM (Q,K bf16 hi/lo, P^T bf16
//      hi/lo); blocks [192,1216): K3a pos-proj stream -> logw fp32.
// k23: FUSED aff+softmax: per (g, 64n) block, loop m: MMA1 (QK^T, 3-term),
//      logits = 0.125*aff + logw, exp WITHOUT max-subtraction (logits bounded
//      << 88), write unnormalized exp bf16 hi/lo + rowsum. No aff tensor.
// k4 : out = (exp @ P^T) / rowsum + out_b via mma.sync 3-term.
// ---------------------------------------------------------------------------

__device__ float g_logw[1024u * 16u * 1024u];            // 64 MB [n][g][m]
__device__ float g_rowsum[16u * 1024u];                  // [g][n]
__device__ __nv_bfloat16 g_hi [4096u * 1024u];           // input hi split
__device__ __nv_bfloat16 g_lo [4096u * 1024u];           // input lo split
__device__ __nv_bfloat16 g_qkh[2u * 16u * 1024u * 64u];  // Q,K hi [seg][g][n][64]
__device__ __nv_bfloat16 g_qkl[2u * 16u * 1024u * 64u];  // Q,K lo
__device__ __nv_bfloat16 g_ph [16u * 64u * 1024u];       // P^T hi [g][o][k]
__device__ __nv_bfloat16 g_pl [16u * 64u * 1024u];       // P^T lo
__device__ __nv_bfloat16 g_sh [16u * 1024u * 1024u];     // exp hi [g][n][m]
__device__ __nv_bfloat16 g_sl [16u * 1024u * 1024u];     // exp lo

// ---- packed f32x2 helpers ---------------------------------------------------
__device__ __forceinline__ unsigned long long pack2(float a, float b) {
    unsigned long long r;
    asm("mov.b64 %0, {%1, %2};" : "=l"(r)
        : "r"(__float_as_uint(a)), "r"(__float_as_uint(b)));
    return r;
}
__device__ __forceinline__ void unpack2(unsigned long long v, float& a, float& b) {
    unsigned int lo, hi;
    asm("mov.b64 {%0, %1}, %2;" : "=r"(lo), "=r"(hi) : "l"(v));
    a = __uint_as_float(lo);
    b = __uint_as_float(hi);
}
__device__ __forceinline__ unsigned long long fma2(unsigned long long a,
                                                   unsigned long long b,
                                                   unsigned long long c) {
    unsigned long long d;
    asm("fma.rn.f32x2 %0, %1, %2, %3;" : "=l"(d) : "l"(a), "l"(b), "l"(c));
    return d;
}

// ---- mma.sync / cp.async helpers --------------------------------------------
__device__ __forceinline__ uint32_t smem_u32(const void* p) {
    uint32_t a;
    asm("{ .reg .u64 t; cvta.to.shared.u64 t, %1; cvt.u32.u64 %0, t; }"
        : "=r"(a) : "l"(p));
    return a;
}
#define CP16(s, g) \
    asm volatile("cp.async.cg.shared.global [%0], [%1], 16;" \
                 :: "r"(s), "l"(g) : "memory")
#define CP_COMMIT() asm volatile("cp.async.commit_group;" ::: "memory")
#define CP_WAIT(n)  asm volatile("cp.async.wait_group %0;" :: "n"(n) : "memory")
#define LDSM4(r, a) \
    asm volatile("ldmatrix.sync.aligned.m8n8.x4.shared.b16 {%0,%1,%2,%3}, [%4];" \
                 : "=r"((r)[0]), "=r"((r)[1]), "=r"((r)[2]), "=r"((r)[3]) \
                 : "r"(a))
#define MMA_BF16(d, a, b0, b1) \
    asm volatile("mma.sync.aligned.m16n8k16.row.col.f32.bf16.bf16.f32 " \
                 "{%0,%1,%2,%3}, {%4,%5,%6,%7}, {%8,%9}, {%0,%1,%2,%3};" \
                 : "+f"((d)[0]), "+f"((d)[1]), "+f"((d)[2]), "+f"((d)[3]) \
                 : "r"((a)[0]), "r"((a)[1]), "r"((a)[2]), "r"((a)[3]), \
                   "r"(b0), "r"(b1))

// 64B-row swizzle: 4 chunks of 16B permuted by row pair.
__device__ __forceinline__ uint32_t swz(int r, int c) {
    return (uint32_t)(r * 64 + (((c ^ ((r >> 1) & 3)) & 3) << 4));
}
// 128B-row SW128 swizzle.
__device__ __forceinline__ uint32_t sw128(uint32_t off) {
    return off ^ ((off >> 3) & 0x70);
}

// ---------------------------------------------------------------------------
// k0: split [roi; q_w; k_w; out_w] into bf16 hi + lo.
// ---------------------------------------------------------------------------
__global__ __launch_bounds__(256) void k0_convert(
    const float* __restrict__ roi, const float* __restrict__ qw,
    const float* __restrict__ kw,  const float* __restrict__ ow)
{
    const size_t e = ((size_t)blockIdx.x * 256 + threadIdx.x) * 4;
    const float* src;
    size_t off;
    if (e < (1u << 20))      { src = roi; off = e; }
    else if (e < (2u << 20)) { src = qw;  off = e - (1u << 20); }
    else if (e < (3u << 20)) { src = kw;  off = e - (2u << 20); }
    else                     { src = ow;  off = e - (3u << 20); }
    const float4 v = *(const float4*)(src + off);
    float x[4] = {v.x, v.y, v.z, v.w};
    __nv_bfloat16 h[4], l[4];
#pragma unroll
    for (int i = 0; i < 4; i++) {
        h[i] = __float2bfloat16(x[i]);
        l[i] = __float2bfloat16(x[i] - __bfloat162float(h[i]));
    }
    ((__nv_bfloat162*)(g_hi + e))[0] = __nv_bfloat162(h[0], h[1]);
    ((__nv_bfloat162*)(g_hi + e))[1] = __nv_bfloat162(h[2], h[3]);
    ((__nv_bfloat162*)(g_lo + e))[0] = __nv_bfloat162(l[0], l[1]);
    ((__nv_bfloat162*)(g_lo + e))[1] = __nv_bfloat162(l[2], l[3]);
}

// ---------------------------------------------------------------------------
// K1 path pieces (used inside k13).
// ---------------------------------------------------------------------------
#define K1_STAGE 32768
#define K1_DSMEM 67584

__device__ __forceinline__ void k1_issue(uint32_t so, int row0, int col0,
                                         int kc, int tid)
{
#pragma unroll
    for (int j = 0; j < 2; j++) {
        const int id = tid + (j << 8);
        const int r = id >> 2, c = id & 3;
        const uint32_t s = so + swz(r, c);
        const size_t goA = (size_t)(row0 + r) * 1024 + (kc << 5) + (c << 3);
        const size_t goB = (size_t)(1024 + col0 + r) * 1024 + (kc << 5) + (c << 3);
        CP16(s,         g_hi + goA);
        CP16(s +  8192, g_lo + goA);
        CP16(s + 16384, g_hi + goB);
        CP16(s + 24576, g_lo + goB);
    }
    CP_COMMIT();
}

__device__ __forceinline__ void k1_compute(uint32_t so, float acc[4][4][4],
                                           int wm, int wn, int lane)
{
    const int arow = lane & 15;
    const int achk = lane >> 4;
#pragma unroll
    for (int ks = 0; ks < 2; ks++) {
        uint32_t ah[4][4], al[4][4], bh[2][4], bl[2][4];
#pragma unroll
        for (int mi = 0; mi < 4; mi++) {
            const int r = wm * 64 + mi * 16 + arow;
            const uint32_t addr = so + swz(r, ks * 2 + achk);
            LDSM4(ah[mi], addr);
            LDSM4(al[mi], addr + 8192);
        }
#pragma unroll
        for (int nj = 0; nj < 2; nj++) {
            const int r = wn * 32 + nj * 16 + arow;
            const uint32_t addr = so + 16384 + swz(r, ks * 2 + achk);
            LDSM4(bh[nj], addr);
            LDSM4(bl[nj], addr + 8192);
        }
#pragma unroll
        for (int mi = 0; mi < 4; mi++)
#pragma unroll
            for (int n = 0; n < 4; n++) {
                const int nj = n >> 1, sb = n & 1;
                MMA_BF16(acc[mi][n], ah[mi], bh[nj][sb], bh[nj][sb + 2]);
                MMA_BF16(acc[mi][n], ah[mi], bl[nj][sb], bl[nj][sb + 2]);
                MMA_BF16(acc[mi][n], al[mi], bh[nj][sb], bh[nj][sb + 2]);
            }
    }
}

// ---------------------------------------------------------------------------
// k13: uber-kernel. blocks [0,192) = K1 GEMM; blocks [192,1216) = K3a stream.
// ---------------------------------------------------------------------------
__global__ __launch_bounds__(256, 2) void k13(
    const float* __restrict__ qb, const float* __restrict__ kb,
    const float* __restrict__ pe, const float* __restrict__ pw,
    const float* __restrict__ pb)
{
    extern __shared__ char sm1[];
    const int tid = threadIdx.x;

    if (blockIdx.x < 192) {
        // =========================== K1 path ================================
        __shared__ float sbias[128];
        const uint32_t sbase = smem_u32(sm1);
        const int lane = tid & 31, wid = tid >> 5;
        const int wm = wid >> 2, wn = wid & 3;
        const int col0 = (blockIdx.x % 24) << 7;
        const int row0 = (blockIdx.x / 24) << 7;
        const int seg = col0 >> 10, jb0 = col0 & 1023;

        if (tid < 128)
            sbias[tid] = (seg == 0) ? qb[jb0 + tid]
                       : ((seg == 1) ? kb[jb0 + tid] : 0.0f);

        float acc[4][4][4];
#pragma unroll
        for (int i = 0; i < 4; i++)
#pragma unroll
            for (int j = 0; j < 4; j++)
#pragma unroll
                for (int q = 0; q < 4; q++) acc[i][j][q] = 0.0f;

        k1_issue(sbase, row0, col0, 0, tid);

#pragma unroll 1
        for (int kc = 0; kc < 32; kc++) {
            const uint32_t so = sbase + ((kc & 1) ? (uint32_t)K1_STAGE : 0u);
            if (kc < 31) {
                k1_issue(sbase + (((kc + 1) & 1) ? (uint32_t)K1_STAGE : 0u),
                         row0, col0, kc + 1, tid);
                CP_WAIT(1);
            } else {
                CP_WAIT(0);
            }
            __syncthreads();
            k1_compute(so, acc, wm, wn, lane);
            __syncthreads();
        }

        if (seg < 2) {
#pragma unroll
            for (int mi = 0; mi < 4; mi++) {
                const int r0 = row0 + wm * 64 + mi * 16 + (lane >> 2);
#pragma unroll
                for (int n = 0; n < 4; n++) {
                    const int lc = wn * 32 + n * 8 + ((lane & 3) << 1);
                    const int jl = jb0 + lc;
                    const int g = jl >> 6, d0 = jl & 63;
                    const float b0 = sbias[lc], b1 = sbias[lc + 1];
                    const float f00 = acc[mi][n][0] + b0;
                    const float f01 = acc[mi][n][1] + b1;
                    const float f10 = acc[mi][n][2] + b0;
                    const float f11 = acc[mi][n][3] + b1;
                    const size_t bi = ((size_t)(seg * 16 + g) * 1024) * 64 + d0;
                    __nv_bfloat16 h00 = __float2bfloat16(f00);
                    __nv_bfloat16 h01 = __float2bfloat16(f01);
                    __nv_bfloat16 h10 = __float2bfloat16(f10);
                    __nv_bfloat16 h11 = __float2bfloat16(f11);
                    *(__nv_bfloat162*)(g_qkh + bi + (size_t)r0 * 64) =
                        __nv_bfloat162(h00, h01);
                    *(__nv_bfloat162*)(g_qkh + bi + (size_t)(r0 + 8) * 64) =
                        __nv_bfloat162(h10, h11);
                    *(__nv_bfloat162*)(g_qkl + bi + (size_t)r0 * 64) =
                        __nv_bfloat162(
                            __float2bfloat16(f00 - __bfloat162float(h00)),
                            __float2bfloat16(f01 - __bfloat162float(h01)));
                    *(__nv_bfloat162*)(g_qkl + bi + (size_t)(r0 + 8) * 64) =
                        __nv_bfloat162(
                            __float2bfloat16(f10 - __bfloat162float(h10)),
                            __float2bfloat16(f11 - __bfloat162float(h11)));
                }
            }
        } else {
            // transpose through smem: smf[col][row] stride 132
            float* smf = (float*)sm1;
#pragma unroll
            for (int mi = 0; mi < 4; mi++) {
                const int rl = wm * 64 + mi * 16 + (lane >> 2);
#pragma unroll
                for (int n = 0; n < 4; n++) {
                    const int lc = wn * 32 + n * 8 + ((lane & 3) << 1);
                    smf[lc * 132 + rl]           = acc[mi][n][0];
                    smf[(lc + 1) * 132 + rl]     = acc[mi][n][1];
                    smf[lc * 132 + rl + 8]       = acc[mi][n][2];
                    smf[(lc + 1) * 132 + rl + 8] = acc[mi][n][3];
                }
            }
            __syncthreads();
            const int c = tid >> 1, half = tid & 1;
            const int jl = jb0 + c;
            const int g = jl >> 6, o = jl & 63;
            __nv_bfloat16* dh = g_ph + ((size_t)g * 64 + o) * 1024 +
                                row0 + half * 64;
            __nv_bfloat16* dl = g_pl + ((size_t)g * 64 + o) * 1024 +
                                row0 + half * 64;
            const float* srow = smf + c * 132 + half * 64;
#pragma unroll
            for (int i4 = 0; i4 < 16; i4++) {
                const float4 v = *(const float4*)(srow + i4 * 4);
                __nv_bfloat16 h0 = __float2bfloat16(v.x);
                __nv_bfloat16 h1 = __float2bfloat16(v.y);
                __nv_bfloat16 h2 = __float2bfloat16(v.z);
                __nv_bfloat16 h3 = __float2bfloat16(v.w);
                ((__nv_bfloat162*)(dh + i4 * 4))[0] = __nv_bfloat162(h0, h1);
                ((__nv_bfloat162*)(dh + i4 * 4))[1] = __nv_bfloat162(h2, h3);
                ((__nv_bfloat162*)(dl + i4 * 4))[0] = __nv_bfloat162(
                    __float2bfloat16(v.x - __bfloat162float(h0)),
                    __float2bfloat16(v.y - __bfloat162float(h1)));
                ((__nv_bfloat162*)(dl + i4 * 4))[1] = __nv_bfloat162(
                    __float2bfloat16(v.z - __bfloat162float(h2)),
                    __float2bfloat16(v.w - __bfloat162float(h3)));
            }
        }
    } else {
        // =========================== K3a path ===============================
        __shared__ ulonglong2 swd2[16][32];
        __shared__ float sb3[16];
        const int n = blockIdx.x - 192;

        for (int idx = tid; idx < 1024; idx += 256) {
            const float w = pw[idx];
            ((unsigned long long*)swd2)[idx] = pack2(w, w);
        }
        if (tid < 16) sb3[tid] = pb[tid];
        __syncthreads();

        const int m0 = tid << 2;
        unsigned long long acc[16][2];
#pragma unroll
        for (int gg = 0; gg < 16; gg++) { acc[gg][0] = 0ULL; acc[gg][1] = 0ULL; }

        const float* base = pe + (size_t)n * 1024 + m0;
        ulonglong2 cur[8];
#pragma unroll
        for (int j = 0; j < 8; j++)
            cur[j] = __ldg((const ulonglong2*)(base + (size_t)j * 1048576));

#pragma unroll 1
        for (int e0 = 0; e0 < 64; e0 += 8) {
            ulonglong2 nxt[8];
            const int eb = (e0 + 8) & 63;
#pragma unroll
            for (int j = 0; j < 8; j++)
                nxt[j] = __ldg((const ulonglong2*)
                               (base + (size_t)(eb + j) * 1048576));
#pragma unroll
            for (int j = 0; j < 8; j += 2) {
                const ulonglong2 c0 = cur[j], c1 = cur[j + 1];
                const int ep = (e0 + j) >> 1;
#pragma unroll
                for (int gg = 0; gg < 16; gg++) {
                    const ulonglong2 w = swd2[gg][ep];
                    acc[gg][0] = fma2(w.x, c0.x, acc[gg][0]);
                    acc[gg][0] = fma2(w.y, c1.x, acc[gg][0]);
                    acc[gg][1] = fma2(w.x, c0.y, acc[gg][1]);
                    acc[gg][1] = fma2(w.y, c1.y, acc[gg][1]);
                }
            }
#pragma unroll
            for (int j = 0; j < 8; j++) cur[j] = nxt[j];
        }

        float* lwp = g_logw + (size_t)n * 16 * 1024 + m0;
#pragma unroll
        for (int gg = 0; gg < 16; gg++) {
            float x0, x1, x2, x3;
            unpack2(acc[gg][0], x0, x1);
            unpack2(acc[gg][1], x2, x3);
            const float bgg = sb3[gg];
            float4 o;
            o.x = __logf(fmaxf(x0 + bgg, 1e-6f));
            o.y = __logf(fmaxf(x1 + bgg, 1e-6f));
            o.z = __logf(fmaxf(x2 + bgg, 1e-6f));
            o.w = __logf(fmaxf(x3 + bgg, 1e-6f));
            *(float4*)(lwp + (size_t)gg * 1024) = o;
        }
    }
}

// ---------------------------------------------------------------------------
// k23: fused aff + softmax (no max-subtraction, logits bounded).
// Block = (g, 64 n-rows); m looped in 16 chunks of 64.
// smem: Q hi/lo 16K @0; 2 stages @16K: [Kh 8K | Kl 8K | logw 64x68 f32 17408].
// 8 warps (2n x 4m): warp tile 32n x 16m.
// ---------------------------------------------------------------------------
#define K23_STAGE 33792
#define K23_ST0   16384
#define K23_LWOFF 16384
#define K23_DSMEM (K23_ST0 + 2 * K23_STAGE)

__device__ __forceinline__ void k23_issue(uint32_t so, char* dummy, int g,
                                          int n0, int m0, int tid)
{
    // K chunk: 64 rows x 128B, hi+lo
#pragma unroll
    for (int j = 0; j < 2; j++) {
        const int id = tid + (j << 8);
        const int r = id >> 3, c = id & 7;
        const size_t go = ((size_t)((16 + g) * 1024) + m0 + r) * 64 + (c << 3);
        const uint32_t s = so + sw128((r << 7) + (c << 4));
        CP16(s,        g_qkh + go);
        CP16(s + 8192, g_qkl + go);
    }
    // logw chunk: 64 n-rows x 64 m fp32, row stride 272B (68 floats)
#pragma unroll
    for (int j = 0; j < 4; j++) {
        const int id = tid + (j << 8);
        const int r = id >> 4, c = id & 15;
        CP16(so + K23_LWOFF + r * 272 + (c << 4),
             g_logw + ((size_t)(n0 + r) * 16 + g) * 1024 + m0 + (c << 2));
    }
    CP_COMMIT();
}

__global__ __launch_bounds__(256, 2) void k23_mma()
{
    extern __shared__ char sm23[];
    __shared__ float srow[64];
    const uint32_t sbase = smem_u32(sm23);
    const int tid = threadIdx.x, lane = tid & 31, wid = tid >> 5;
    const int wm = wid >> 2, wn = wid & 3;
    const int n0 = blockIdx.x << 6, g = blockIdx.y;

    if (tid < 64) srow[tid] = 0.0f;

    // Q tile prologue (uncommitted; joins stage-0 group)
#pragma unroll
    for (int j = 0; j < 2; j++) {
        const int id = tid + (j << 8);
        const int r = id >> 3, c = id & 7;
        const size_t go = ((size_t)(g * 1024) + n0 + r) * 64 + (c << 3);
        const uint32_t s = sbase + sw128((r << 7) + (c << 4));
        CP16(s,        g_qkh + go);
        CP16(s + 8192, g_qkl + go);
    }
    k23_issue(sbase + K23_ST0, sm23, g, n0, 0, tid);

    const int arow = lane & 15, achk = lane >> 4;
    const int rbase = wm * 32 + (lane >> 2);        // + mi*16 + p*8
    const int cbase = wn * 16 + ((lane & 3) << 1);  // + nj*8
    float rs[4] = {0.0f, 0.0f, 0.0f, 0.0f};

#pragma unroll 1
    for (int kc = 0; kc < 16; kc++) {
        const uint32_t so = sbase + K23_ST0 + (kc & 1) * (uint32_t)K23_STAGE;
        char* lwb = sm23 + (so - sbase) + K23_LWOFF;
        if (kc < 15) {
            k23_issue(sbase + K23_ST0 + ((kc + 1) & 1) * (uint32_t)K23_STAGE,
                      sm23, g, n0, (kc + 1) << 6, tid);
            CP_WAIT(1);
        } else {
            CP_WAIT(0);
        }
        __syncthreads();

        float acc[2][2][4];
#pragma unroll
        for (int i = 0; i < 2; i++)
#pragma unroll
            for (int j = 0; j < 2; j++)
#pragma unroll
                for (int q = 0; q < 4; q++) acc[i][j][q] = 0.0f;

#pragma unroll
        for (int ks = 0; ks < 4; ks++) {
            uint32_t ah[2][4], al[2][4], bh[4], bl[4];
#pragma unroll
            for (int mi = 0; mi < 2; mi++) {
                const int r = wm * 32 + mi * 16 + arow;
                const uint32_t addr =
                    sbase + sw128((r << 7) + (ks << 5) + (achk << 4));
                LDSM4(ah[mi], addr);
                LDSM4(al[mi], addr + 8192);
            }
            {
                const int r = wn * 16 + arow;
                const uint32_t addr =
                    so + sw128((r << 7) + (ks << 5) + (achk << 4));
                LDSM4(bh, addr);
                LDSM4(bl, addr + 8192);
            }
#pragma unroll
            for (int mi = 0; mi < 2; mi++)
#pragma unroll
                for (int nj = 0; nj < 2; nj++) {
                    MMA_BF16(acc[mi][nj], ah[mi], bh[nj], bh[nj + 2]);
                    MMA_BF16(acc[mi][nj], ah[mi], bl[nj], bl[nj + 2]);
                    MMA_BF16(acc[mi][nj], al[mi], bh[nj], bh[nj + 2]);
                }
        }

        // epilogue: logits -> exp -> bf16 hi/lo store + rowsum partials
        const int m0 = kc << 6;
#pragma unroll
        for (int mi = 0; mi < 2; mi++)
#pragma unroll
            for (int p = 0; p < 2; p++) {
                const int row = rbase + mi * 16 + p * 8;
#pragma unroll
                for (int nj = 0; nj < 2; nj++) {
                    const int mc = cbase + nj * 8;
                    const float2 lw =
                        *(const float2*)(lwb + row * 272 + (mc << 2));
                    const float e0 = __expf(
                        fmaf(0.125f, acc[mi][nj][p * 2], lw.x));
                    const float e1 = __expf(
                        fmaf(0.125f, acc[mi][nj][p * 2 + 1], lw.y));
                    rs[mi * 2 + p] += e0 + e1;
                    const __nv_bfloat16 h0 = __float2bfloat16(e0);
                    const __nv_bfloat16 h1 = __float2bfloat16(e1);
                    const size_t go =
                        ((size_t)g * 1024 + n0 + row) * 1024 + m0 + mc;
                    *(__nv_bfloat162*)(g_sh + go) = __nv_bfloat162(h0, h1);
                    *(__nv_bfloat162*)(g_sl + go) = __nv_bfloat162(
                        __float2bfloat16(e0 - __bfloat162float(h0)),
                        __float2bfloat16(e1 - __bfloat162float(h1)));
                }
            }
        __syncthreads();
    }

#pragma unroll
    for (int i = 0; i < 4; i++) {
        const int row = rbase + (i >> 1) * 16 + (i & 1) * 8;
        atomicAdd(&srow[row], rs[i]);
    }
    __syncthreads();
    if (tid < 64) g_rowsum[g * 1024 + n0 + tid] = srow[tid];
}

// ---------------------------------------------------------------------------
// k4: out[n][g*64+o] = (sum_k exp[g][n][k] * P^T[g][o][k]) / rowsum + out_b.
// 64n x 64o block, BK=32, 2-stage cp.async.
// ---------------------------------------------------------------------------
#define K4_STAGE 16384
#define K4_DSMEM (2 * K4_STAGE)

__device__ __forceinline__ void k4_issue(uint32_t so, int n0, int g,
                                         int kt, int tid)
{
    const int r = tid >> 2, c = tid & 3;
    const uint32_t s = so + swz(r, c);
    const size_t ga = ((size_t)g * 1024 + n0 + r) * 1024 + kt + (c << 3);
    CP16(s,        g_sh + ga);
    CP16(s + 4096, g_sl + ga);
    const size_t gb = ((size_t)g * 64 + r) * 1024 + kt + (c << 3);
    CP16(s + 8192,  g_ph + gb);
    CP16(s + 12288, g_pl + gb);
    CP_COMMIT();
}

__global__ __launch_bounds__(256, 2) void k4_mma(float* __restrict__ out,
                                                 const float* __restrict__ obias)
{
    extern __shared__ char sm4[];
    __shared__ float sbias[64];
    __shared__ float sinv[64];
    const uint32_t sbase = smem_u32(sm4);
    const int tid = threadIdx.x, lane = tid & 31, wid = tid >> 5;
    const int wm = wid >> 2, wn = wid & 3;
    const int n0 = blockIdx.x << 6, g = blockIdx.y;

    if (tid < 64) {
        sbias[tid] = obias[(g << 6) + tid];
        sinv[tid] = __fdividef(1.0f, g_rowsum[g * 1024 + n0 + tid]);
    }

    float acc[2][2][4];
#pragma unroll
    for (int i = 0; i < 2; i++)
#pragma unroll
        for (int j = 0; j < 2; j++)
#pragma unroll
            for (int q = 0; q < 4; q++) acc[i][j][q] = 0.0f;

    k4_issue(sbase, n0, g, 0, tid);

    const int arow = lane & 15, achk = lane >> 4;
#pragma unroll 1
    for (int kc = 0; kc < 32; kc++) {
        const uint32_t so = sbase + ((kc & 1) ? (uint32_t)K4_STAGE : 0u);
        if (kc < 31) {
            k4_issue(sbase + (((kc + 1) & 1) ? (uint32_t)K4_STAGE : 0u),
                     n0, g, (kc + 1) << 5, tid);
            CP_WAIT(1);
        } else {
            CP_WAIT(0);
        }
        __syncthreads();
#pragma unroll
        for (int ks = 0; ks < 2; ks++) {
            uint32_t ah[2][4], al[2][4], bh[4], bl[4];
#pragma unroll
            for (int mi = 0; mi < 2; mi++) {
                const int r = wm * 32 + mi * 16 + arow;
                const uint32_t addr = so + swz(r, ks * 2 + achk);
                LDSM4(ah[mi], addr);
                LDSM4(al[mi], addr + 4096);
            }
            {
                const int r = wn * 16 + arow;
                const uint32_t addr = so + 8192 + swz(r, ks * 2 + achk);
                LDSM4(bh, addr);
                LDSM4(bl, addr + 4096);
            }
#pragma unroll
            for (int mi = 0; mi < 2; mi++)
#pragma unroll
                for (int n = 0; n < 2; n++) {
                    MMA_BF16(acc[mi][n], ah[mi], bh[n], bh[n + 2]);
                    MMA_BF16(acc[mi][n], ah[mi], bl[n], bl[n + 2]);
                    MMA_BF16(acc[mi][n], al[mi], bh[n], bh[n + 2]);
                }
        }
        __syncthreads();
    }

#pragma unroll
    for (int mi = 0; mi < 2; mi++) {
        const int rl = wm * 32 + mi * 16 + (lane >> 2);
        const int r0 = n0 + rl;
        const float s0 = sinv[rl], s1 = sinv[rl + 8];
#pragma unroll
        for (int n = 0; n < 2; n++) {
            const int lc = wn * 16 + n * 8 + ((lane & 3) << 1);
            const float b0 = sbias[lc], b1 = sbias[lc + 1];
            float* dst = out + (size_t)r0 * 1024 + (g << 6) + lc;
            dst[0] = fmaf(acc[mi][n][0], s0, b0);
            dst[1] = fmaf(acc[mi][n][1], s0, b1);
            dst[1024 * 8 + 0] = fmaf(acc[mi][n][2], s1, b0);
            dst[1024 * 8 + 1] = fmaf(acc[mi][n][3], s1, b1);
        }
    }
}

// ---------------------------------------------------------------------------
extern "C" void kernel_launch(void* const* d_in, const int* in_sizes, int n_in,
                              void* d_out, int out_size)
{
    const float* roi = (const float*)d_in[0];
    const float* pe  = (const float*)d_in[1];
    int ix = 2;
    if (ix < n_in && in_sizes[ix] == 1) ix++;
    const float* pos_w = (const float*)d_in[ix++];
    const float* pos_b = (const float*)d_in[ix++];
    const float* q_w   = (const float*)d_in[ix++];
    const float* q_b   = (const float*)d_in[ix++];
    const float* k_w   = (const float*)d_in[ix++];
    const float* k_b   = (const float*)d_in[ix++];
    const float* out_w = (const float*)d_in[ix++];
    const float* out_b = (const float*)d_in[ix++];
    float* out = (float*)d_out;

    cudaFuncSetAttribute(k13, cudaFuncAttributeMaxDynamicSharedMemorySize,
                         K1_DSMEM);
    cudaFuncSetAttribute(k23_mma, cudaFuncAttributeMaxDynamicSharedMemorySize,
                         K23_DSMEM);
    cudaFuncSetAttribute(k4_mma, cudaFuncAttributeMaxDynamicSharedMemorySize,
                         K4_DSMEM);

    k0_convert<<<4096,           256>>>(roi, q_w, k_w, out_w);
    k13       <<<1216,           256, K1_DSMEM>>>(q_b, k_b, pe, pos_w, pos_b);
    k23_mma   <<<dim3(16, 16),   256, K23_DSMEM>>>();
    k4_mma    <<<dim3(16, 16),   256, K4_DSMEM>>>(out, out_b);
}

// round 11
// speedup vs baseline: 1.2120x; 1.0932x over previous
#include <cuda_runtime.h>
#include <cuda_bf16.h>
#include <cstdint>

// ---------------------------------------------------------------------------
// RelationNetwork v11.
// k0  : fp32 -> bf16 hi/lo split of [roi; q_w; k_w; out_w]
// k13 : UBER-KERNEL. blocks [0,192): K1 mma GEMM (Q,K bf16 hi/lo, P^T bf16
//       hi/lo); blocks [192,1216): K3a pos-proj stream -> logw fp32.
// k234: FULLY FUSED attention tail. Per (g, 64n) block, loop m-chunks of 64:
//       MMA1 (QK^T 3-term) -> logits = 0.125*aff + logw -> exp (no max-sub,
//       logits bounded) -> exp bf16 hi/lo staged in smem (reusing dead logw
//       region) -> MMA2 accumulates out += exp @ P^T. Final epilogue divides
//       by rowsum, adds bias. exp NEVER touches DRAM.
// ---------------------------------------------------------------------------

__device__ float g_logw[1024u * 16u * 1024u];            // 64 MB [n][g][m]
__device__ __nv_bfloat16 g_hi [4096u * 1024u];           // input hi split
__device__ __nv_bfloat16 g_lo [4096u * 1024u];           // input lo split
__device__ __nv_bfloat16 g_qkh[2u * 16u * 1024u * 64u];  // Q,K hi [seg][g][n][64]
__device__ __nv_bfloat16 g_qkl[2u * 16u * 1024u * 64u];  // Q,K lo
__device__ __nv_bfloat16 g_ph [16u * 64u * 1024u];       // P^T hi [g][o][k]
__device__ __nv_bfloat16 g_pl [16u * 64u * 1024u];       // P^T lo

// ---- packed f32x2 helpers ---------------------------------------------------
__device__ __forceinline__ unsigned long long pack2(float a, float b) {
    unsigned long long r;
    asm("mov.b64 %0, {%1, %2};" : "=l"(r)
        : "r"(__float_as_uint(a)), "r"(__float_as_uint(b)));
    return r;
}
__device__ __forceinline__ void unpack2(unsigned long long v, float& a, float& b) {
    unsigned int lo, hi;
    asm("mov.b64 {%0, %1}, %2;" : "=r"(lo), "=r"(hi) : "l"(v));
    a = __uint_as_float(lo);
    b = __uint_as_float(hi);
}
__device__ __forceinline__ unsigned long long fma2(unsigned long long a,
                                                   unsigned long long b,
                                                   unsigned long long c) {
    unsigned long long d;
    asm("fma.rn.f32x2 %0, %1, %2, %3;" : "=l"(d) : "l"(a), "l"(b), "l"(c));
    return d;
}

// ---- mma.sync / cp.async helpers --------------------------------------------
__device__ __forceinline__ uint32_t smem_u32(const void* p) {
    uint32_t a;
    asm("{ .reg .u64 t; cvta.to.shared.u64 t, %1; cvt.u32.u64 %0, t; }"
        : "=r"(a) : "l"(p));
    return a;
}
#define CP16(s, g) \
    asm volatile("cp.async.cg.shared.global [%0], [%1], 16;" \
                 :: "r"(s), "l"(g) : "memory")
#define CP_COMMIT() asm volatile("cp.async.commit_group;" ::: "memory")
#define CP_WAIT(n)  asm volatile("cp.async.wait_group %0;" :: "n"(n) : "memory")
#define LDSM4(r, a) \
    asm volatile("ldmatrix.sync.aligned.m8n8.x4.shared.b16 {%0,%1,%2,%3}, [%4];" \
                 : "=r"((r)[0]), "=r"((r)[1]), "=r"((r)[2]), "=r"((r)[3]) \
                 : "r"(a))
#define MMA_BF16(d, a, b0, b1) \
    asm volatile("mma.sync.aligned.m16n8k16.row.col.f32.bf16.bf16.f32 " \
                 "{%0,%1,%2,%3}, {%4,%5,%6,%7}, {%8,%9}, {%0,%1,%2,%3};" \
                 : "+f"((d)[0]), "+f"((d)[1]), "+f"((d)[2]), "+f"((d)[3]) \
                 : "r"((a)[0]), "r"((a)[1]), "r"((a)[2]), "r"((a)[3]), \
                   "r"(b0), "r"(b1))

// 64B-row swizzle: 4 chunks of 16B permuted by row pair.
__device__ __forceinline__ uint32_t swz(int r, int c) {
    return (uint32_t)(r * 64 + (((c ^ ((r >> 1) & 3)) & 3) << 4));
}
// 128B-row SW128 swizzle.
__device__ __forceinline__ uint32_t sw128(uint32_t off) {
    return off ^ ((off >> 3) & 0x70);
}

// ---------------------------------------------------------------------------
// k0: split [roi; q_w; k_w; out_w] into bf16 hi + lo.
// ---------------------------------------------------------------------------
__global__ __launch_bounds__(256) void k0_convert(
    const float* __restrict__ roi, const float* __restrict__ qw,
    const float* __restrict__ kw,  const float* __restrict__ ow)
{
    const size_t e = ((size_t)blockIdx.x * 256 + threadIdx.x) * 4;
    const float* src;
    size_t off;
    if (e < (1u << 20))      { src = roi; off = e; }
    else if (e < (2u << 20)) { src = qw;  off = e - (1u << 20); }
    else if (e < (3u << 20)) { src = kw;  off = e - (2u << 20); }
    else                     { src = ow;  off = e - (3u << 20); }
    const float4 v = *(const float4*)(src + off);
    float x[4] = {v.x, v.y, v.z, v.w};
    __nv_bfloat16 h[4], l[4];
#pragma unroll
    for (int i = 0; i < 4; i++) {
        h[i] = __float2bfloat16(x[i]);
        l[i] = __float2bfloat16(x[i] - __bfloat162float(h[i]));
    }
    ((__nv_bfloat162*)(g_hi + e))[0] = __nv_bfloat162(h[0], h[1]);
    ((__nv_bfloat162*)(g_hi + e))[1] = __nv_bfloat162(h[2], h[3]);
    ((__nv_bfloat162*)(g_lo + e))[0] = __nv_bfloat162(l[0], l[1]);
    ((__nv_bfloat162*)(g_lo + e))[1] = __nv_bfloat162(l[2], l[3]);
}

// ---------------------------------------------------------------------------
// K1 path pieces (used inside k13).
// ---------------------------------------------------------------------------
#define K1_STAGE 32768
#define K1_DSMEM 67584

__device__ __forceinline__ void k1_issue(uint32_t so, int row0, int col0,
                                         int kc, int tid)
{
#pragma unroll
    for (int j = 0; j < 2; j++) {
        const int id = tid + (j << 8);
        const int r = id >> 2, c = id & 3;
        const uint32_t s = so + swz(r, c);
        const size_t goA = (size_t)(row0 + r) * 1024 + (kc << 5) + (c << 3);
        const size_t goB = (size_t)(1024 + col0 + r) * 1024 + (kc << 5) + (c << 3);
        CP16(s,         g_hi + goA);
        CP16(s +  8192, g_lo + goA);
        CP16(s + 16384, g_hi + goB);
        CP16(s + 24576, g_lo + goB);
    }
    CP_COMMIT();
}

__device__ __forceinline__ void k1_compute(uint32_t so, float acc[4][4][4],
                                           int wm, int wn, int lane)
{
    const int arow = lane & 15;
    const int achk = lane >> 4;
#pragma unroll
    for (int ks = 0; ks < 2; ks++) {
        uint32_t ah[4][4], al[4][4], bh[2][4], bl[2][4];
#pragma unroll
        for (int mi = 0; mi < 4; mi++) {
            const int r = wm * 64 + mi * 16 + arow;
            const uint32_t addr = so + swz(r, ks * 2 + achk);
            LDSM4(ah[mi], addr);
            LDSM4(al[mi], addr + 8192);
        }
#pragma unroll
        for (int nj = 0; nj < 2; nj++) {
            const int r = wn * 32 + nj * 16 + arow;
            const uint32_t addr = so + 16384 + swz(r, ks * 2 + achk);
            LDSM4(bh[nj], addr);
            LDSM4(bl[nj], addr + 8192);
        }
#pragma unroll
        for (int mi = 0; mi < 4; mi++)
#pragma unroll
            for (int n = 0; n < 4; n++) {
                const int nj = n >> 1, sb = n & 1;
                MMA_BF16(acc[mi][n], ah[mi], bh[nj][sb], bh[nj][sb + 2]);
                MMA_BF16(acc[mi][n], ah[mi], bl[nj][sb], bl[nj][sb + 2]);
                MMA_BF16(acc[mi][n], al[mi], bh[nj][sb], bh[nj][sb + 2]);
            }
    }
}

// ---------------------------------------------------------------------------
// k13: uber-kernel. blocks [0,192) = K1 GEMM; blocks [192,1216) = K3a stream.
// ---------------------------------------------------------------------------
__global__ __launch_bounds__(256, 2) void k13(
    const float* __restrict__ qb, const float* __restrict__ kb,
    const float* __restrict__ pe, const float* __restrict__ pw,
    const float* __restrict__ pb)
{
    extern __shared__ char sm1[];
    const int tid = threadIdx.x;

    if (blockIdx.x < 192) {
        // =========================== K1 path ================================
        __shared__ float sbias[128];
        const uint32_t sbase = smem_u32(sm1);
        const int lane = tid & 31, wid = tid >> 5;
        const int wm = wid >> 2, wn = wid & 3;
        const int col0 = (blockIdx.x % 24) << 7;
        const int row0 = (blockIdx.x / 24) << 7;
        const int seg = col0 >> 10, jb0 = col0 & 1023;

        if (tid < 128)
            sbias[tid] = (seg == 0) ? qb[jb0 + tid]
                       : ((seg == 1) ? kb[jb0 + tid] : 0.0f);

        float acc[4][4][4];
#pragma unroll
        for (int i = 0; i < 4; i++)
#pragma unroll
            for (int j = 0; j < 4; j++)
#pragma unroll
                for (int q = 0; q < 4; q++) acc[i][j][q] = 0.0f;

        k1_issue(sbase, row0, col0, 0, tid);

#pragma unroll 1
        for (int kc = 0; kc < 32; kc++) {
            const uint32_t so = sbase + ((kc & 1) ? (uint32_t)K1_STAGE : 0u);
            if (kc < 31) {
                k1_issue(sbase + (((kc + 1) & 1) ? (uint32_t)K1_STAGE : 0u),
                         row0, col0, kc + 1, tid);
                CP_WAIT(1);
            } else {
                CP_WAIT(0);
            }
            __syncthreads();
            k1_compute(so, acc, wm, wn, lane);
            __syncthreads();
        }

        if (seg < 2) {
#pragma unroll
            for (int mi = 0; mi < 4; mi++) {
                const int r0 = row0 + wm * 64 + mi * 16 + (lane >> 2);
#pragma unroll
                for (int n = 0; n < 4; n++) {
                    const int lc = wn * 32 + n * 8 + ((lane & 3) << 1);
                    const int jl = jb0 + lc;
                    const int g = jl >> 6, d0 = jl & 63;
                    const float b0 = sbias[lc], b1 = sbias[lc + 1];
                    const float f00 = acc[mi][n][0] + b0;
                    const float f01 = acc[mi][n][1] + b1;
                    const float f10 = acc[mi][n][2] + b0;
                    const float f11 = acc[mi][n][3] + b1;
                    const size_t bi = ((size_t)(seg * 16 + g) * 1024) * 64 + d0;
                    __nv_bfloat16 h00 = __float2bfloat16(f00);
                    __nv_bfloat16 h01 = __float2bfloat16(f01);
                    __nv_bfloat16 h10 = __float2bfloat16(f10);
                    __nv_bfloat16 h11 = __float2bfloat16(f11);
                    *(__nv_bfloat162*)(g_qkh + bi + (size_t)r0 * 64) =
                        __nv_bfloat162(h00, h01);
                    *(__nv_bfloat162*)(g_qkh + bi + (size_t)(r0 + 8) * 64) =
                        __nv_bfloat162(h10, h11);
                    *(__nv_bfloat162*)(g_qkl + bi + (size_t)r0 * 64) =
                        __nv_bfloat162(
                            __float2bfloat16(f00 - __bfloat162float(h00)),
                            __float2bfloat16(f01 - __bfloat162float(h01)));
                    *(__nv_bfloat162*)(g_qkl + bi + (size_t)(r0 + 8) * 64) =
                        __nv_bfloat162(
                            __float2bfloat16(f10 - __bfloat162float(h10)),
                            __float2bfloat16(f11 - __bfloat162float(h11)));
                }
            }
        } else {
            // transpose through smem: smf[col][row] stride 132
            float* smf = (float*)sm1;
#pragma unroll
            for (int mi = 0; mi < 4; mi++) {
                const int rl = wm * 64 + mi * 16 + (lane >> 2);
#pragma unroll
                for (int n = 0; n < 4; n++) {
                    const int lc = wn * 32 + n * 8 + ((lane & 3) << 1);
                    smf[lc * 132 + rl]           = acc[mi][n][0];
                    smf[(lc + 1) * 132 + rl]     = acc[mi][n][1];
                    smf[lc * 132 + rl + 8]       = acc[mi][n][2];
                    smf[(lc + 1) * 132 + rl + 8] = acc[mi][n][3];
                }
            }
            __syncthreads();
            const int c = tid >> 1, half = tid & 1;
            const int jl = jb0 + c;
            const int g = jl >> 6, o = jl & 63;
            __nv_bfloat16* dh = g_ph + ((size_t)g * 64 + o) * 1024 +
                                row0 + half * 64;
            __nv_bfloat16* dl = g_pl + ((size_t)g * 64 + o) * 1024 +
                                row0 + half * 64;
            const float* srow = smf + c * 132 + half * 64;
#pragma unroll
            for (int i4 = 0; i4 < 16; i4++) {
                const float4 v = *(const float4*)(srow + i4 * 4);
                __nv_bfloat16 h0 = __float2bfloat16(v.x);
                __nv_bfloat16 h1 = __float2bfloat16(v.y);
                __nv_bfloat16 h2 = __float2bfloat16(v.z);
                __nv_bfloat16 h3 = __float2bfloat16(v.w);
                ((__nv_bfloat162*)(dh + i4 * 4))[0] = __nv_bfloat162(h0, h1);
                ((__nv_bfloat162*)(dh + i4 * 4))[1] = __nv_bfloat162(h2, h3);
                ((__nv_bfloat162*)(dl + i4 * 4))[0] = __nv_bfloat162(
                    __float2bfloat16(v.x - __bfloat162float(h0)),
                    __float2bfloat16(v.y - __bfloat162float(h1)));
                ((__nv_bfloat162*)(dl + i4 * 4))[1] = __nv_bfloat162(
                    __float2bfloat16(v.z - __bfloat162float(h2)),
                    __float2bfloat16(v.w - __bfloat162float(h3)));
            }
        }
    } else {
        // =========================== K3a path ===============================
        __shared__ ulonglong2 swd2[16][32];
        __shared__ float sb3[16];
        const int n = blockIdx.x - 192;

        for (int idx = tid; idx < 1024; idx += 256) {
            const float w = pw[idx];
            ((unsigned long long*)swd2)[idx] = pack2(w, w);
        }
        if (tid < 16) sb3[tid] = pb[tid];
        __syncthreads();

        const int m0 = tid << 2;
        unsigned long long acc[16][2];
#pragma unroll
        for (int gg = 0; gg < 16; gg++) { acc[gg][0] = 0ULL; acc[gg][1] = 0ULL; }

        const float* base = pe + (size_t)n * 1024 + m0;
        ulonglong2 cur[8];
#pragma unroll
        for (int j = 0; j < 8; j++)
            cur[j] = __ldg((const ulonglong2*)(base + (size_t)j * 1048576));

#pragma unroll 1
        for (int e0 = 0; e0 < 64; e0 += 8) {
            ulonglong2 nxt[8];
            const int eb = (e0 + 8) & 63;
#pragma unroll
            for (int j = 0; j < 8; j++)
                nxt[j] = __ldg((const ulonglong2*)
                               (base + (size_t)(eb + j) * 1048576));
#pragma unroll
            for (int j = 0; j < 8; j += 2) {
                const ulonglong2 c0 = cur[j], c1 = cur[j + 1];
                const int ep = (e0 + j) >> 1;
#pragma unroll
                for (int gg = 0; gg < 16; gg++) {
                    const ulonglong2 w = swd2[gg][ep];
                    acc[gg][0] = fma2(w.x, c0.x, acc[gg][0]);
                    acc[gg][0] = fma2(w.y, c1.x, acc[gg][0]);
                    acc[gg][1] = fma2(w.x, c0.y, acc[gg][1]);
                    acc[gg][1] = fma2(w.y, c1.y, acc[gg][1]);
                }
            }
#pragma unroll
            for (int j = 0; j < 8; j++) cur[j] = nxt[j];
        }

        float* lwp = g_logw + (size_t)n * 16 * 1024 + m0;
#pragma unroll
        for (int gg = 0; gg < 16; gg++) {
            float x0, x1, x2, x3;
            unpack2(acc[gg][0], x0, x1);
            unpack2(acc[gg][1], x2, x3);
            const float bgg = sb3[gg];
            float4 o;
            o.x = __logf(fmaxf(x0 + bgg, 1e-6f));
            o.y = __logf(fmaxf(x1 + bgg, 1e-6f));
            o.z = __logf(fmaxf(x2 + bgg, 1e-6f));
            o.w = __logf(fmaxf(x3 + bgg, 1e-6f));
            *(float4*)(lwp + (size_t)gg * 1024) = o;
        }
    }
}

// ---------------------------------------------------------------------------
// k234: fused aff + softmax + output GEMM. Block = (g, 64n).
// smem: Q hi/lo 16K @0 | 2 stages @16K (each: Kh 8K, Kl 8K, logw 64x68f 17K;
// exp bf16 hi/lo reuses the logw area after it is consumed) | P hi/lo 16K.
// Pipeline groups: [Q+S0], [P0], then per-iter [S(kc+1)] and end-of-iter
// [P(kc+1)] (P single-buffered; overwrite point is the post-MMA2 barrier).
// ---------------------------------------------------------------------------
#define K234_ST0   16384
#define K234_STAGE 33792
#define K234_LWOFF 16384
#define K234_POFF  (K234_ST0 + 2 * K234_STAGE)      // 83968
#define K234_DSMEM (K234_POFF + 16384)              // 100352

__device__ __forceinline__ void k234_issueS(uint32_t so, int g, int n0,
                                            int m0, int tid)
{
    // K chunk: 64 m-rows x 64 d (128B rows), hi+lo
#pragma unroll
    for (int j = 0; j < 2; j++) {
        const int id = tid + (j << 8);
        const int r = id >> 3, c = id & 7;
        const size_t go = ((size_t)((16 + g) * 1024) + m0 + r) * 64 + (c << 3);
        const uint32_t s = so + sw128((r << 7) + (c << 4));
        CP16(s,        g_qkh + go);
        CP16(s + 8192, g_qkl + go);
    }
    // logw chunk: 64 n-rows x 64 m fp32, row stride 272B
#pragma unroll
    for (int j = 0; j < 4; j++) {
        const int id = tid + (j << 8);
        const int r = id >> 4, c = id & 15;
        CP16(so + K234_LWOFF + r * 272 + (c << 4),
             g_logw + ((size_t)(n0 + r) * 16 + g) * 1024 + m0 + (c << 2));
    }
    CP_COMMIT();
}

__device__ __forceinline__ void k234_issueP(uint32_t sp, int g, int m0, int tid)
{
#pragma unroll
    for (int j = 0; j < 2; j++) {
        const int id = tid + (j << 8);
        const int r = id >> 3, c = id & 7;
        const size_t gb = ((size_t)g * 64 + r) * 1024 + m0 + (c << 3);
        const uint32_t s = sp + sw128((r << 7) + (c << 4));
        CP16(s,        g_ph + gb);
        CP16(s + 8192, g_pl + gb);
    }
    CP_COMMIT();
}

__global__ __launch_bounds__(256, 2) void k234(float* __restrict__ out,
                                               const float* __restrict__ obias)
{
    extern __shared__ char smx[];
    __shared__ float srow[64];
    __shared__ float sbias[64];
    const uint32_t sbase = smem_u32(smx);
    const int tid = threadIdx.x, lane = tid & 31, wid = tid >> 5;
    const int wm = wid >> 2, wn = wid & 3;
    const int n0 = blockIdx.x << 6, g = blockIdx.y;

    if (tid < 64) {
        srow[tid] = 0.0f;
        sbias[tid] = obias[(g << 6) + tid];
    }

    // Q prologue (joins S0's commit group)
#pragma unroll
    for (int j = 0; j < 2; j++) {
        const int id = tid + (j << 8);
        const int r = id >> 3, c = id & 7;
        const size_t go = ((size_t)(g * 1024) + n0 + r) * 64 + (c << 3);
        const uint32_t s = sbase + sw128((r << 7) + (c << 4));
        CP16(s,        g_qkh + go);
        CP16(s + 8192, g_qkl + go);
    }
    k234_issueS(sbase + K234_ST0, g, n0, 0, tid);
    k234_issueP(sbase + K234_POFF, g, 0, tid);

    const int arow = lane & 15, achk = lane >> 4;
    const int rbase = wm * 32 + (lane >> 2);
    const int cbase = wn * 16 + ((lane & 3) << 1);

    float acc2[2][2][4];
#pragma unroll
    for (int i = 0; i < 2; i++)
#pragma unroll
        for (int j = 0; j < 2; j++)
#pragma unroll
            for (int q = 0; q < 4; q++) acc2[i][j][q] = 0.0f;
    float rs[4] = {0.0f, 0.0f, 0.0f, 0.0f};

#pragma unroll 1
    for (int kc = 0; kc < 16; kc++) {
        const uint32_t so = sbase + K234_ST0 + (kc & 1) * (uint32_t)K234_STAGE;
        char* lwb = smx + (so - sbase) + K234_LWOFF;
        if (kc < 15) {
            k234_issueS(sbase + K234_ST0 + ((kc + 1) & 1) * (uint32_t)K234_STAGE,
                        g, n0, (kc + 1) << 6, tid);
            CP_WAIT(1);
        } else {
            CP_WAIT(0);
        }
        __syncthreads();

        // ---- MMA1: aff chunk (Q vs K), 3-term split ----
        float acc1[2][2][4];
#pragma unroll
        for (int i = 0; i < 2; i++)
#pragma unroll
            for (int j = 0; j < 2; j++)
#pragma unroll
                for (int q = 0; q < 4; q++) acc1[i][j][q] = 0.0f;

#pragma unroll
        for (int ks = 0; ks < 4; ks++) {
            uint32_t ah[2][4], al[2][4], bh[4], bl[4];
#pragma unroll
            for (int mi = 0; mi < 2; mi++) {
                const int r = wm * 32 + mi * 16 + arow;
                const uint32_t addr =
                    sbase + sw128((r << 7) + (ks << 5) + (achk << 4));
                LDSM4(ah[mi], addr);
                LDSM4(al[mi], addr + 8192);
            }
            {
                const int r = wn * 16 + arow;
                const uint32_t addr =
                    so + sw128((r << 7) + (ks << 5) + (achk << 4));
                LDSM4(bh, addr);
                LDSM4(bl, addr + 8192);
            }
#pragma unroll
            for (int mi = 0; mi < 2; mi++)
#pragma unroll
                for (int nj = 0; nj < 2; nj++) {
                    MMA_BF16(acc1[mi][nj], ah[mi], bh[nj], bh[nj + 2]);
                    MMA_BF16(acc1[mi][nj], ah[mi], bl[nj], bl[nj + 2]);
                    MMA_BF16(acc1[mi][nj], al[mi], bh[nj], bh[nj + 2]);
                }
        }

        // ---- logits -> exp (in regs) + rowsum partials ----
#pragma unroll
        for (int mi = 0; mi < 2; mi++)
#pragma unroll
            for (int p = 0; p < 2; p++) {
                const int row = rbase + mi * 16 + p * 8;
#pragma unroll
                for (int nj = 0; nj < 2; nj++) {
                    const int mc = cbase + nj * 8;
                    const float2 lw =
                        *(const float2*)(lwb + row * 272 + (mc << 2));
                    const float e0 = __expf(
                        fmaf(0.125f, acc1[mi][nj][p * 2], lw.x));
                    const float e1 = __expf(
                        fmaf(0.125f, acc1[mi][nj][p * 2 + 1], lw.y));
                    rs[mi * 2 + p] += e0 + e1;
                    acc1[mi][nj][p * 2]     = e0;
                    acc1[mi][nj][p * 2 + 1] = e1;
                }
            }
        __syncthreads();   // all logw reads done before exp overwrites region

        // ---- store exp bf16 hi/lo into the (dead) logw region ----
        char* expb = lwb;  // 16K used of the 17K logw area
#pragma unroll
        for (int mi = 0; mi < 2; mi++)
#pragma unroll
            for (int p = 0; p < 2; p++) {
                const int row = rbase + mi * 16 + p * 8;
#pragma unroll
                for (int nj = 0; nj < 2; nj++) {
                    const int mc = cbase + nj * 8;
                    const float e0 = acc1[mi][nj][p * 2];
                    const float e1 = acc1[mi][nj][p * 2 + 1];
                    const __nv_bfloat16 h0 = __float2bfloat16(e0);
                    const __nv_bfloat16 h1 = __float2bfloat16(e1);
                    const uint32_t off = sw128((row << 7) + (mc << 1));
                    *(__nv_bfloat162*)(expb + off) = __nv_bfloat162(h0, h1);
                    *(__nv_bfloat162*)(expb + 8192 + off) = __nv_bfloat162(
                        __float2bfloat16(e0 - __bfloat162float(h0)),
                        __float2bfloat16(e1 - __bfloat162float(h1)));
                }
            }
        __syncthreads();   // exp visible to all warps

        // ---- MMA2: out += exp @ P^T, 3-term split ----
        const uint32_t ea = so + K234_LWOFF;
        const uint32_t pa = sbase + K234_POFF;
#pragma unroll
        for (int ks = 0; ks < 4; ks++) {
            uint32_t ah[2][4], al[2][4], bh[4], bl[4];
#pragma unroll
            for (int mi = 0; mi < 2; mi++) {
                const int r = wm * 32 + mi * 16 + arow;
                const uint32_t addr =
                    ea + sw128((r << 7) + (ks << 5) + (achk << 4));
                LDSM4(ah[mi], addr);
                LDSM4(al[mi], addr + 8192);
            }
            {
                const int r = wn * 16 + arow;
                const uint32_t addr =
                    pa + sw128((r << 7) + (ks << 5) + (achk << 4));
                LDSM4(bh, addr);
                LDSM4(bl, addr + 8192);
            }
#pragma unroll
            for (int mi = 0; mi < 2; mi++)
#pragma unroll
                for (int nj = 0; nj < 2; nj++) {
                    MMA_BF16(acc2[mi][nj], ah[mi], bh[nj], bh[nj + 2]);
                    MMA_BF16(acc2[mi][nj], ah[mi], bl[nj], bl[nj + 2]);
                    MMA_BF16(acc2[mi][nj], al[mi], bh[nj], bh[nj + 2]);
                }
        }
        __syncthreads();   // P buffer free to overwrite

        if (kc < 15)
            k234_issueP(pa, g, (kc + 1) << 6, tid);
    }

    // ---- rowsum reduction + normalized output with bias ----
#pragma unroll
    for (int i = 0; i < 4; i++) {
        const int row = rbase + (i >> 1) * 16 + (i & 1) * 8;
        atomicAdd(&srow[row], rs[i]);
    }
    __syncthreads();
    if (tid < 64) srow[tid] = __fdividef(1.0f, srow[tid]);
    __syncthreads();

#pragma unroll
    for (int mi = 0; mi < 2; mi++) {
        const int rl = wm * 32 + mi * 16 + (lane >> 2);
        const int r0 = n0 + rl;
        const float s0 = srow[rl], s1 = srow[rl + 8];
#pragma unroll
        for (int nj = 0; nj < 2; nj++) {
            const int lc = wn * 16 + nj * 8 + ((lane & 3) << 1);
            const float b0 = sbias[lc], b1 = sbias[lc + 1];
            float* dst = out + (size_t)r0 * 1024 + (g << 6) + lc;
            dst[0] = fmaf(acc2[mi][nj][0], s0, b0);
            dst[1] = fmaf(acc2[mi][nj][1], s0, b1);
            dst[1024 * 8 + 0] = fmaf(acc2[mi][nj][2], s1, b0);
            dst[1024 * 8 + 1] = fmaf(acc2[mi][nj][3], s1, b1);
        }
    }
}

// ---------------------------------------------------------------------------
extern "C" void kernel_launch(void* const* d_in, const int* in_sizes, int n_in,
                              void* d_out, int out_size)
{
    const float* roi = (const float*)d_in[0];
    const float* pe  = (const float*)d_in[1];
    int ix = 2;
    if (ix < n_in && in_sizes[ix] == 1) ix++;
    const float* pos_w = (const float*)d_in[ix++];
    const float* pos_b = (const float*)d_in[ix++];
    const float* q_w   = (const float*)d_in[ix++];
    const float* q_b   = (const float*)d_in[ix++];
    const float* k_w   = (const float*)d_in[ix++];
    const float* k_b   = (const float*)d_in[ix++];
    const float* out_w = (const float*)d_in[ix++];
    const float* out_b = (const float*)d_in[ix++];
    float* out = (float*)d_out;

    cudaFuncSetAttribute(k13, cudaFuncAttributeMaxDynamicSharedMemorySize,
                         K1_DSMEM);
    cudaFuncSetAttribute(k234, cudaFuncAttributeMaxDynamicSharedMemorySize,
                         K234_DSMEM);

    k0_convert<<<4096,         256>>>(roi, q_w, k_w, out_w);
    k13       <<<1216,         256, K1_DSMEM>>>(q_b, k_b, pe, pos_w, pos_b);
    k234      <<<dim3(16, 16), 256, K234_DSMEM>>>(out, out_b);
}